// round 14
// baseline (speedup 1.0000x reference)
#include <cuda_runtime.h>
#include <cuda_bf16.h>
#include <cstdint>

#define NP 100      // proxies
#define NS 1024     // samples
#define NN 1124     // total nodes
#define MPAD 1152   // NN padded to 128
#define D  512
#define KPAD2 128   // NP padded for sample-agg K
#define PSPLIT 9    // proxy-agg split-K (9 x 128 = 1152)

#define GRID 148
#define NVB 296     // virtual blocks (2 per physical block)

#define STAGE_BYTES 32768
#define AGG_SMEM (2 * STAGE_BYTES + 16384)   // 81920: stages + fp32 self tile
#define SCRATCH_OFF AGG_SMEM
#define SUB_SMEM (AGG_SMEM + 8192)           // 90112 per sub-block
#define MEGA_SMEM (2 * SUB_SMEM)             // 180224

// scratch (device globals; no allocation allowed)
__device__ float g_HW[MPAD * D];
__device__ float g_aselfS[NS];
__device__ float g_lp[8][NN][2];
__device__ float g_ppart[PSPLIT][128][D];
__device__ unsigned g_barc[16];
__device__ unsigned g_barg[16];
// bf16 split operands
__device__ __nv_bfloat16 g_Ah[MPAD * D];
__device__ __nv_bfloat16 g_Al[MPAD * D];
__device__ __nv_bfloat16 g_W1h[D * D];
__device__ __nv_bfloat16 g_W1l[D * D];
__device__ __nv_bfloat16 g_W2h[D * D];
__device__ __nv_bfloat16 g_W2l[D * D];
__device__ __nv_bfloat16 g_FCh[128 * D];
__device__ __nv_bfloat16 g_FCl[128 * D];
__device__ __nv_bfloat16 g_Hth[D * MPAD];
__device__ __nv_bfloat16 g_Htl[D * MPAD];
__device__ __nv_bfloat16 g_aSh[NS * KPAD2];
__device__ __nv_bfloat16 g_aSl[NS * KPAD2];
__device__ __nv_bfloat16 g_aPh[128 * MPAD];
__device__ __nv_bfloat16 g_aPl[128 * MPAD];

__device__ __forceinline__ float lrelu(float v) { return v > 0.f ? v : 0.2f * v; }

__device__ __forceinline__ uint32_t smem_u32(const void* p) {
    uint32_t a;
    asm("{ .reg .u64 t; cvta.to.shared.u64 t, %1; cvt.u32.u64 %0, t; }" : "=r"(a) : "l"(p));
    return a;
}
__device__ __forceinline__ void bsplit(float v, __nv_bfloat16& hi, __nv_bfloat16& lo) {
    hi = __float2bfloat16(v);
    lo = __float2bfloat16(v - __bfloat162float(hi));
}

#define BSYNC(bid) asm volatile("bar.sync %0, 256;" :: "r"(bid) : "memory")

// grid-wide sense-reversal barrier (148 arrivals; generation survives graph replays)
__device__ __forceinline__ void gridbar(int i) {
    __syncthreads();
    if (threadIdx.x == 0) {
        __threadfence();
        volatile unsigned* vg = g_barg;
        unsigned gen = vg[i];
        if (atomicAdd(&g_barc[i], 1u) == GRID - 1) {
            g_barc[i] = 0;
            __threadfence();
            atomicAdd(&g_barg[i], 1u);
        } else {
            while (vg[i] == gen) {}
        }
        __threadfence();
    }
    __syncthreads();
}

// ============================ mma primitives ============================
#define SWB(r, b) ((r) * 128 + ((b) ^ (((r) & 7) << 4)))

__device__ __forceinline__ void ldm_x4(uint32_t* f, uint32_t addr) {
    asm volatile("ldmatrix.sync.aligned.m8n8.x4.shared.b16 {%0,%1,%2,%3}, [%4];"
                 : "=r"(f[0]), "=r"(f[1]), "=r"(f[2]), "=r"(f[3]) : "r"(addr));
}
__device__ __forceinline__ void ldm_x2(uint32_t* f, uint32_t addr) {
    asm volatile("ldmatrix.sync.aligned.m8n8.x2.shared.b16 {%0,%1}, [%2];"
                 : "=r"(f[0]), "=r"(f[1]) : "r"(addr));
}
__device__ __forceinline__ void mma_bf16(float* c, const uint32_t* a, const uint32_t* b) {
    asm volatile(
        "mma.sync.aligned.m16n8k16.row.col.f32.bf16.bf16.f32 "
        "{%0,%1,%2,%3}, {%4,%5,%6,%7}, {%8,%9}, {%0,%1,%2,%3};"
        : "+f"(c[0]), "+f"(c[1]), "+f"(c[2]), "+f"(c[3])
        : "r"(a[0]), "r"(a[1]), "r"(a[2]), "r"(a[3]), "r"(b[0]), "r"(b[1]));
}
__device__ __forceinline__ void cpa16(uint32_t saddr, const void* g) {
    asm volatile("cp.async.cg.shared.global [%0], [%1], 16;" :: "r"(saddr), "l"(g));
}

#define MMA_MAINLOOP(AH, AL, BH, BL, LDA, LDB, NCHUNK, KOFF)                             \
    int li = tid * 2;                                                                    \
    int lr0 = li >> 3, ls0 = li & 7;                                                     \
    int lr1 = (li + 1) >> 3, ls1 = (li + 1) & 7;                                         \
    int a_r = (lane & 7) + ((lane >> 3) & 1) * 8;                                        \
    int a_kb = (lane >> 4) * 16;                                                         \
    int b_r = lane & 7;                                                                  \
    int b_kb = ((lane >> 3) & 1) * 16;                                                   \
    float acc[2][2][4] = {};                                                             \
    auto issue = [&](int c, int st) {                                                    \
        int kc = (KOFF) + c * 64;                                                        \
        uint32_t stb = sb + st * STAGE_BYTES;                                            \
        cpa16(stb + SWB(lr0, ls0 * 16), (AH) + (size_t)(m0 + lr0) * (LDA) + kc + ls0 * 8); \
        cpa16(stb + SWB(lr1, ls1 * 16), (AH) + (size_t)(m0 + lr1) * (LDA) + kc + ls1 * 8); \
        cpa16(stb + 8192 + SWB(lr0, ls0 * 16), (AL) + (size_t)(m0 + lr0) * (LDA) + kc + ls0 * 8); \
        cpa16(stb + 8192 + SWB(lr1, ls1 * 16), (AL) + (size_t)(m0 + lr1) * (LDA) + kc + ls1 * 8); \
        cpa16(stb + 16384 + SWB(lr0, ls0 * 16), (BH) + (size_t)(n0 + lr0) * (LDB) + kc + ls0 * 8); \
        cpa16(stb + 16384 + SWB(lr1, ls1 * 16), (BH) + (size_t)(n0 + lr1) * (LDB) + kc + ls1 * 8); \
        cpa16(stb + 24576 + SWB(lr0, ls0 * 16), (BL) + (size_t)(n0 + lr0) * (LDB) + kc + ls0 * 8); \
        cpa16(stb + 24576 + SWB(lr1, ls1 * 16), (BL) + (size_t)(n0 + lr1) * (LDB) + kc + ls1 * 8); \
        asm volatile("cp.async.commit_group;");                                          \
    };                                                                                   \
    issue(0, 0);                                                                         \
    asm volatile("cp.async.wait_group 0;");                                              \
    BSYNC(barid);                                                                        \
    for (int c = 0; c < (NCHUNK); c++) {                                                 \
        int st = c & 1;                                                                  \
        if (c + 1 < (NCHUNK)) issue(c + 1, st ^ 1);                                      \
        uint32_t stb = sb + st * STAGE_BYTES;                                            \
        _Pragma("unroll")                                                                \
        for (int ks = 0; ks < 4; ks++) {                                                 \
            int kb = ks * 32;                                                            \
            uint32_t ah[2][4], al[2][4], bh[2][2], bl[2][2];                             \
            _Pragma("unroll")                                                            \
            for (int mt = 0; mt < 2; mt++) {                                             \
                int r = wm + mt * 16 + a_r;                                              \
                ldm_x4(ah[mt], stb + 0    + SWB(r, kb + a_kb));                          \
                ldm_x4(al[mt], stb + 8192 + SWB(r, kb + a_kb));                          \
            }                                                                            \
            _Pragma("unroll")                                                            \
            for (int nt = 0; nt < 2; nt++) {                                             \
                int r = wn + nt * 8 + b_r;                                               \
                ldm_x2(bh[nt], stb + 16384 + SWB(r, kb + b_kb));                         \
                ldm_x2(bl[nt], stb + 24576 + SWB(r, kb + b_kb));                         \
            }                                                                            \
            _Pragma("unroll")                                                            \
            for (int mt = 0; mt < 2; mt++)                                               \
                _Pragma("unroll")                                                        \
                for (int nt = 0; nt < 2; nt++) {                                         \
                    mma_bf16(acc[mt][nt], ah[mt], bh[nt]);                               \
                    mma_bf16(acc[mt][nt], ah[mt], bl[nt]);                               \
                    mma_bf16(acc[mt][nt], al[mt], bh[nt]);                               \
                }                                                                        \
        }                                                                                \
        if (c + 1 < (NCHUNK)) asm volatile("cp.async.wait_group 0;");                    \
        BSYNC(barid);                                                                    \
    }

// ============================ phase: setup unit ============================
__device__ __noinline__ void setup_unit(int u, int tid, int barid, char* ssm,
                                        const float* W1, const float* W2,
                                        const float* fcw,
                                        const float* x, const float* prox) {
    float* t = reinterpret_cast<float*>(ssm + SCRATCH_OFF);   // [32][33]
    if (u < 512) {
        const float* W = (u >= 256) ? W2 : W1;
        __nv_bfloat16* Wh = (u >= 256) ? g_W2h : g_W1h;
        __nv_bfloat16* Wl = (u >= 256) ? g_W2l : g_W1l;
        int bb = u & 255;
        int tx = tid & 31, ty = tid >> 5;
        int n0 = (bb & 15) * 32, k0 = (bb >> 4) * 32;
        #pragma unroll
        for (int j = 0; j < 4; j++)
            t[(ty + 8 * j) * 33 + tx] = W[(size_t)(k0 + ty + 8 * j) * D + n0 + tx];
        BSYNC(barid);
        #pragma unroll
        for (int j = 0; j < 4; j++) {
            int n = n0 + ty + 8 * j, k = k0 + tx;
            __nv_bfloat16 hi, lo;
            bsplit(t[tx * 33 + ty + 8 * j], hi, lo);
            Wh[(size_t)n * D + k] = hi;
            Wl[(size_t)n * D + k] = lo;
        }
        BSYNC(barid);
    } else if (u < 576) {
        int bb = u - 512;
        int tx = tid & 31, ty = tid >> 5;
        int n0 = (bb & 3) * 32, k0 = (bb >> 2) * 32;
        #pragma unroll
        for (int j = 0; j < 4; j++) {
            int n = n0 + tx;
            t[(ty + 8 * j) * 33 + tx] = (n < 100) ? fcw[(size_t)(k0 + ty + 8 * j) * 100 + n] : 0.f;
        }
        BSYNC(barid);
        #pragma unroll
        for (int j = 0; j < 4; j++) {
            int n = n0 + ty + 8 * j, k = k0 + tx;
            __nv_bfloat16 hi, lo;
            bsplit(t[tx * 33 + ty + 8 * j], hi, lo);
            g_FCh[(size_t)n * D + k] = hi;
            g_FCl[(size_t)n * D + k] = lo;
        }
        BSYNC(barid);
    } else {
        int row = (u - 576) * 2 + (tid >> 7);
        int c4 = (tid & 127) * 4;
        int base = row * D + c4;
        float4 v = make_float4(0.f, 0.f, 0.f, 0.f);
        if (row < NP)      v = *reinterpret_cast<const float4*>(prox + base);
        else if (row < NN) v = *reinterpret_cast<const float4*>(x + base - NP * D);
        __nv_bfloat16 h0, h1, h2, h3, l0, l1, l2, l3;
        bsplit(v.x, h0, l0); bsplit(v.y, h1, l1); bsplit(v.z, h2, l2); bsplit(v.w, h3, l3);
        *reinterpret_cast<__nv_bfloat162*>(g_Ah + base)     = __nv_bfloat162(h0, h1);
        *reinterpret_cast<__nv_bfloat162*>(g_Ah + base + 2) = __nv_bfloat162(h2, h3);
        *reinterpret_cast<__nv_bfloat162*>(g_Al + base)     = __nv_bfloat162(l0, l1);
        *reinterpret_cast<__nv_bfloat162*>(g_Al + base + 2) = __nv_bfloat162(l2, l3);
    }
}

// ============================ phase: layer/FC GEMM tile ============================
__device__ __noinline__ void mma_tile(int tid, int barid, char* ssm, int m0, int n0,
                                      const __nv_bfloat16* Ah, const __nv_bfloat16* Al,
                                      const __nv_bfloat16* Bh, const __nv_bfloat16* Bl,
                                      float* C, const float* bias, int mode,
                                      const float* asrc, const float* adst) {
    int wid = tid >> 5, lane = tid & 31;
    int wm = (wid >> 2) * 32, wn = (wid & 3) * 16;
    uint32_t sb = smem_u32(ssm);

    MMA_MAINLOOP(Ah, Al, Bh, Bl, D, D, 8, 0)

    if (mode == 0) {
        #pragma unroll
        for (int mt = 0; mt < 2; mt++) {
            int row = m0 + wm + mt * 16 + (lane >> 2);
            #pragma unroll
            for (int nt = 0; nt < 2; nt++) {
                int col = n0 + wn + nt * 8 + (lane & 3) * 2;
                if (col >= 100) continue;
                float b0 = bias[col], b1 = bias[col + 1];
                *reinterpret_cast<float2*>(C + (size_t)row * 100 + col) =
                    make_float2(acc[mt][nt][0] + b0, acc[mt][nt][1] + b1);
                *reinterpret_cast<float2*>(C + (size_t)(row + 8) * 100 + col) =
                    make_float2(acc[mt][nt][2] + b0, acc[mt][nt][3] + b1);
            }
        }
        return;
    }

    // fp32 HW store
    #pragma unroll
    for (int mt = 0; mt < 2; mt++) {
        int row = m0 + wm + mt * 16 + (lane >> 2);
        #pragma unroll
        for (int nt = 0; nt < 2; nt++) {
            int col = n0 + wn + nt * 8 + (lane & 3) * 2;
            *reinterpret_cast<float2*>(g_HW + (size_t)row * D + col) =
                make_float2(acc[mt][nt][0], acc[mt][nt][1]);
            *reinterpret_cast<float2*>(g_HW + (size_t)(row + 8) * D + col) =
                make_float2(acc[mt][nt][2], acc[mt][nt][3]);
        }
    }

    // logit partials
    {
        float* lpb = reinterpret_cast<float*>(ssm);   // [64][4][2]
        #pragma unroll
        for (int mt = 0; mt < 2; mt++)
            #pragma unroll
            for (int half = 0; half < 2; half++) {
                int rl = wm + mt * 16 + (lane >> 2) + half * 8;
                float s = 0.f, t = 0.f;
                #pragma unroll
                for (int nt = 0; nt < 2; nt++) {
                    int col = n0 + wn + nt * 8 + (lane & 3) * 2;
                    float v0 = acc[mt][nt][half * 2], v1 = acc[mt][nt][half * 2 + 1];
                    s += v0 * asrc[col] + v1 * asrc[col + 1];
                    t += v0 * adst[col] + v1 * adst[col + 1];
                }
                s += __shfl_xor_sync(0xffffffffu, s, 1);
                s += __shfl_xor_sync(0xffffffffu, s, 2);
                t += __shfl_xor_sync(0xffffffffu, t, 1);
                t += __shfl_xor_sync(0xffffffffu, t, 2);
                if ((lane & 3) == 0) {
                    lpb[(rl * 4 + (wid & 3)) * 2 + 0] = s;
                    lpb[(rl * 4 + (wid & 3)) * 2 + 1] = t;
                }
            }
        BSYNC(barid);
        if (tid < 128) {
            int rl = tid >> 1, comp = tid & 1;
            int row = m0 + rl;
            if (row < NN) {
                float s = lpb[(rl * 4 + 0) * 2 + comp] + lpb[(rl * 4 + 1) * 2 + comp]
                        + lpb[(rl * 4 + 2) * 2 + comp] + lpb[(rl * 4 + 3) * 2 + comp];
                g_lp[n0 >> 6][row][comp] = s;
            }
        }
        BSYNC(barid);
    }

    // transpose via smem, write Ht bf16 split
    float* ts = reinterpret_cast<float*>(ssm);   // [64][65]
    #pragma unroll
    for (int mt = 0; mt < 2; mt++)
        #pragma unroll
        for (int nt = 0; nt < 2; nt++)
            #pragma unroll
            for (int j = 0; j < 4; j++) {
                int rl = wm + mt * 16 + (lane >> 2) + (j >> 1) * 8;
                int cl = wn + nt * 8 + (lane & 3) * 2 + (j & 1);
                ts[rl * 65 + cl] = acc[mt][nt][j];
            }
    BSYNC(barid);
    #pragma unroll
    for (int it = 0; it < 16; it++) {
        int lin = it * 256 + tid;
        int n = lin >> 6, m = lin & 63;
        __nv_bfloat16 hi, lo;
        bsplit(ts[m * 65 + n], hi, lo);
        g_Hth[(size_t)(n0 + n) * MPAD + m0 + m] = hi;
        g_Htl[(size_t)(n0 + n) * MPAD + m0 + m] = lo;
    }
    BSYNC(barid);
}

// ============================ phase: alpha ============================
__device__ __noinline__ void alpha_block(int tid, int barid, char* ssm, int b) {
    float* scr = reinterpret_cast<float*>(ssm + SCRATCH_OFF);
    if (b < 128) {
        float* lsp = scr;          // [128]
        if (tid < NP) {
            float s = 0.f;
            #pragma unroll
            for (int ti = 0; ti < 8; ti++)
                s += __ldcg(reinterpret_cast<const float2*>(&g_lp[ti][tid][0])).x;
            lsp[tid] = s;
        }
        BSYNC(barid);
        int warp = b * 8 + (tid >> 5);
        int lane = tid & 31;
        int node = NP + warp;
        float lsn = 0.f, ldn = 0.f;
        #pragma unroll
        for (int ti = 0; ti < 8; ti++) {
            float2 v = __ldcg(reinterpret_cast<const float2*>(&g_lp[ti][node][0]));
            lsn += v.x;
            ldn += v.y;
        }
        float w[4], sum = 0.f;
        #pragma unroll
        for (int i = 0; i < 4; i++) {
            int p = lane + 32 * i;
            w[i] = (p < NP) ? __expf(lrelu(lsp[p] + ldn)) : 0.f;
            sum += w[i];
        }
        float wself = __expf(lrelu(lsn + ldn));
        #pragma unroll
        for (int o = 16; o > 0; o >>= 1) sum += __shfl_xor_sync(0xffffffffu, sum, o);
        float inv = 1.f / (sum + wself);
        #pragma unroll
        for (int i = 0; i < 4; i++) {
            int p = lane + 32 * i;
            __nv_bfloat16 hi, lo;
            bsplit(w[i] * inv, hi, lo);
            g_aSh[(size_t)warp * KPAD2 + p] = hi;
            g_aSl[(size_t)warp * KPAD2 + p] = lo;
        }
        if (lane == 0) g_aselfS[warp] = wself * inv;
        BSYNC(barid);
    } else if (b < 228) {
        float* sh = scr + 128;     // [8]
        float* s_inv = scr + 136;
        int p = b - 128;
        float ldp = 0.f, lspp = 0.f;
        #pragma unroll
        for (int ti = 0; ti < 8; ti++) {
            float2 v = __ldcg(reinterpret_cast<const float2*>(&g_lp[ti][p][0]));
            lspp += v.x;
            ldp += v.y;
        }
        float w[4], sum = 0.f;
        #pragma unroll
        for (int i = 0; i < 4; i++) {
            int s = tid + i * 256;
            float ls = 0.f;
            #pragma unroll
            for (int ti = 0; ti < 8; ti++)
                ls += __ldcg(reinterpret_cast<const float2*>(&g_lp[ti][NP + s][0])).x;
            w[i] = __expf(lrelu(ls + ldp));
            sum += w[i];
        }
        float wself = __expf(lrelu(lspp + ldp));
        #pragma unroll
        for (int o = 16; o > 0; o >>= 1) sum += __shfl_xor_sync(0xffffffffu, sum, o);
        if ((tid & 31) == 0) sh[tid >> 5] = sum;
        BSYNC(barid);
        if (tid == 0) {
            float ss = 0.f;
            #pragma unroll
            for (int i = 0; i < 8; i++) ss += sh[i];
            s_inv[0] = 1.f / (ss + wself);
        }
        BSYNC(barid);
        float inv = s_inv[0];
        #pragma unroll
        for (int i = 0; i < 4; i++) {
            int col = NP + tid + i * 256;
            __nv_bfloat16 hi, lo;
            bsplit(w[i] * inv, hi, lo);
            g_aPh[(size_t)p * MPAD + col] = hi;
            g_aPl[(size_t)p * MPAD + col] = lo;
        }
        if (tid < NP) {
            float dv = (tid == p) ? wself * inv : 0.f;
            __nv_bfloat16 hi, lo;
            bsplit(dv, hi, lo);
            g_aPh[(size_t)p * MPAD + tid] = hi;
            g_aPl[(size_t)p * MPAD + tid] = lo;
        }
        if (tid < MPAD - NN) {
            __nv_bfloat16 z = __float2bfloat16(0.f);
            g_aPh[(size_t)p * MPAD + NN + tid] = z;
            g_aPl[(size_t)p * MPAD + NN + tid] = z;
        }
    } else {
        int p = 100 + (b - 228);
        uint32_t* h = reinterpret_cast<uint32_t*>(g_aPh + (size_t)p * MPAD);
        uint32_t* l = reinterpret_cast<uint32_t*>(g_aPl + (size_t)p * MPAD);
        for (int i = tid; i < MPAD / 2; i += 256) { h[i] = 0u; l[i] = 0u; }
    }
}

// ============================ phase: aggregation tile ============================
__device__ __noinline__ void aggm_block(int tid, int barid, char* ssm, int b,
                                        const float* bias, float* hout, int layer) {
    int wid = tid >> 5, lane = tid & 31;
    int wm = (wid >> 2) * 32, wn = (wid & 3) * 16;
    uint32_t sb = smem_u32(ssm);

    if (b < 128) {
        int m0 = (b >> 3) * 64, n0 = (b & 7) * 64;

        // prefetch fp32 self tile into ssm+64K (waited by mainloop's wait_group 0)
        #pragma unroll
        for (int q = 0; q < 4; q++) {
            int i = tid + q * 256;
            int r = i >> 4, cc = (i & 15) * 4;
            cpa16(sb + 65536 + i * 16, g_HW + (size_t)(NP + m0 + r) * D + n0 + cc);
        }
        asm volatile("cp.async.commit_group;");

        MMA_MAINLOOP(g_aSh, g_aSl, g_Hth, g_Htl, KPAD2, MPAD, 2, 0)

        const float* selfS = reinterpret_cast<const float*>(ssm + 65536);
        #pragma unroll
        for (int mt = 0; mt < 2; mt++)
            #pragma unroll
            for (int nt = 0; nt < 2; nt++)
                #pragma unroll
                for (int j = 0; j < 4; j++) {
                    int rl = wm + mt * 16 + (lane >> 2) + (j >> 1) * 8;
                    int cl = wn + nt * 8 + (lane & 3) * 2 + (j & 1);
                    float v = acc[mt][nt][j] + __ldcg(&g_aselfS[m0 + rl]) * selfS[rl * 64 + cl]
                            + bias[n0 + cl];
                    acc[mt][nt][j] = v > 0.f ? v : 0.f;
                }
        #pragma unroll
        for (int mt = 0; mt < 2; mt++)
            #pragma unroll
            for (int half = 0; half < 2; half++) {
                int r = m0 + wm + mt * 16 + (lane >> 2) + half * 8;
                int arow = (layer == 1) ? (NP + r) : r;
                #pragma unroll
                for (int nt = 0; nt < 2; nt++) {
                    int col = n0 + wn + nt * 8 + (lane & 3) * 2;
                    float v0 = acc[mt][nt][half * 2], v1 = acc[mt][nt][half * 2 + 1];
                    __nv_bfloat16 h0, h1, l0, l1;
                    bsplit(v0, h0, l0); bsplit(v1, h1, l1);
                    *reinterpret_cast<__nv_bfloat162*>(g_Ah + (size_t)arow * D + col) =
                        __nv_bfloat162(h0, h1);
                    *reinterpret_cast<__nv_bfloat162*>(g_Al + (size_t)arow * D + col) =
                        __nv_bfloat162(l0, l1);
                    if (layer == 2)
                        *reinterpret_cast<float2*>(hout + (size_t)r * D + col) =
                            make_float2(v0, v1);
                }
            }
    } else {
        int bb = b - 128;
        int tile = bb & 15;
        int z = bb >> 4;
        int m0 = (tile >> 3) * 64, n0 = (tile & 7) * 64;
        MMA_MAINLOOP(g_aPh, g_aPl, g_Hth, g_Htl, MPAD, MPAD, 2, z * 128)
        float* part = &g_ppart[z][0][0];
        #pragma unroll
        for (int mt = 0; mt < 2; mt++)
            #pragma unroll
            for (int half = 0; half < 2; half++) {
                int p = m0 + wm + mt * 16 + (lane >> 2) + half * 8;
                if (p >= NP) continue;
                #pragma unroll
                for (int nt = 0; nt < 2; nt++) {
                    int col = n0 + wn + nt * 8 + (lane & 3) * 2;
                    *reinterpret_cast<float2*>(part + (size_t)p * D + col) =
                        make_float2(acc[mt][nt][half * 2], acc[mt][nt][half * 2 + 1]);
                }
            }
    }
}

// ============================ phase: proxy finalize ============================
__device__ __noinline__ void pfin_block(int tid, int b, const float* bias) {
    int idx = b * 256 + tid;
    int p = idx / (D / 2);
    int c = (idx - p * (D / 2)) * 2;
    float v0 = 0.f, v1 = 0.f;
    #pragma unroll
    for (int z = 0; z < PSPLIT; z++) {
        float2 t = __ldcg(reinterpret_cast<const float2*>(&g_ppart[z][p][c]));
        v0 += t.x; v1 += t.y;
    }
    v0 += bias[c];     v0 = v0 > 0.f ? v0 : 0.f;
    v1 += bias[c + 1]; v1 = v1 > 0.f ? v1 : 0.f;
    __nv_bfloat16 h0, h1, l0, l1;
    bsplit(v0, h0, l0); bsplit(v1, h1, l1);
    *reinterpret_cast<__nv_bfloat162*>(g_Ah + (size_t)p * D + c) = __nv_bfloat162(h0, h1);
    *reinterpret_cast<__nv_bfloat162*>(g_Al + (size_t)p * D + c) = __nv_bfloat162(l0, l1);
}

// ============================ the mega kernel ============================
__global__ void __launch_bounds__(512, 1) k_mega(
    const float* __restrict__ W1, const float* __restrict__ W2,
    const float* __restrict__ fcw,
    const float* __restrict__ x, const float* __restrict__ prox,
    const float* __restrict__ as1, const float* __restrict__ ad1,
    const float* __restrict__ b1,
    const float* __restrict__ as2, const float* __restrict__ ad2,
    const float* __restrict__ b2,
    const float* __restrict__ fcb, float* __restrict__ out) {
    extern __shared__ __align__(16) char sm[];
    int sub = threadIdx.x >> 8;
    int tid = threadIdx.x & 255;
    int barid = 1 + sub;
    char* ssm = sm + sub * SUB_SMEM;
    int vb = blockIdx.x * 2 + sub;

    // P0: setup
    for (int u = vb; u < 1152; u += NVB)
        setup_unit(u, tid, barid, ssm, W1, W2, fcw, x, prox);
    gridbar(0);

    // P1: mma layer 1
    if (vb < 144)
        mma_tile(tid, barid, ssm, (vb >> 3) * 64, (vb & 7) * 64,
                 g_Ah, g_Al, g_W1h, g_W1l, nullptr, nullptr, 1, as1, ad1);
    gridbar(1);

    // P2: alpha layer 1 (samples + proxies + pads)
    if (vb < 256) alpha_block(tid, barid, ssm, vb);
    gridbar(2);

    // P3: aggregation layer 1
    if (vb < 272) aggm_block(tid, barid, ssm, vb, b1, nullptr, 1);
    gridbar(3);

    // P4: proxy finalize
    if (vb < 100) pfin_block(tid, vb, b1);
    gridbar(4);

    // P5: mma layer 2
    if (vb < 144)
        mma_tile(tid, barid, ssm, (vb >> 3) * 64, (vb & 7) * 64,
                 g_Ah, g_Al, g_W2h, g_W2l, nullptr, nullptr, 1, as2, ad2);
    gridbar(5);

    // P6: alpha layer 2 (samples only)
    if (vb < 128) alpha_block(tid, barid, ssm, vb);
    gridbar(6);

    // P7: aggregation layer 2 (writes h output)
    if (vb < 128) aggm_block(tid, barid, ssm, vb, b2, out + NS * 100, 2);
    gridbar(7);

    // P8: preds = h @ fc_w + fc_b
    if (vb < 32)
        mma_tile(tid, barid, ssm, (vb >> 1) * 64, (vb & 1) * 64,
                 g_Ah, g_Al, g_FCh, g_FCl, out, fcb, 0, nullptr, nullptr);
}

// ============================ launch ============================
extern "C" void kernel_launch(void* const* d_in, const int* in_sizes, int n_in,
                              void* d_out, int out_size) {
    const float* x    = (const float*)d_in[0];
    const float* prox = (const float*)d_in[1];
    const float* W1   = (const float*)d_in[2];
    const float* as1  = (const float*)d_in[3];
    const float* ad1  = (const float*)d_in[4];
    const float* b1   = (const float*)d_in[5];
    const float* W2   = (const float*)d_in[6];
    const float* as2  = (const float*)d_in[7];
    const float* ad2  = (const float*)d_in[8];
    const float* b2   = (const float*)d_in[9];
    const float* fcw  = (const float*)d_in[10];
    const float* fcb  = (const float*)d_in[11];
    float* out = (float*)d_out;

    cudaFuncSetAttribute(k_mega, cudaFuncAttributeMaxDynamicSharedMemorySize, MEGA_SMEM);
    k_mega<<<GRID, 512, MEGA_SMEM>>>(W1, W2, fcw, x, prox,
                                     as1, ad1, b1, as2, ad2, b2, fcb, out);
}

// round 15
// speedup vs baseline: 1.3640x; 1.3640x over previous
#include <cuda_runtime.h>
#include <cuda_bf16.h>
#include <cstdint>

#define NP 100      // proxies
#define NS 1024     // samples
#define NN 1124     // total nodes
#define MPAD 1152   // NN padded to 128
#define D  512
#define KPAD2 128   // NP padded for sample-agg K
#define PSPLIT 9    // proxy-agg split-K factor (9 x 128 = 1152)

// scratch (device globals; no allocation allowed)
__device__ float g_HW[MPAD * D];
__device__ float g_aselfS[NS];
__device__ float g_lp[8][NN][2];        // logit partials [64col-tile][node][src/dst]
__device__ float g_ppart[PSPLIT][128][D];
// bf16 split operands
__device__ __nv_bfloat16 g_Ah[MPAD * D];
__device__ __nv_bfloat16 g_Al[MPAD * D];
__device__ __nv_bfloat16 g_W1h[D * D];
__device__ __nv_bfloat16 g_W1l[D * D];
__device__ __nv_bfloat16 g_W2h[D * D];
__device__ __nv_bfloat16 g_W2l[D * D];
__device__ __nv_bfloat16 g_FCh[128 * D];
__device__ __nv_bfloat16 g_FCl[128 * D];
__device__ __nv_bfloat16 g_Hth[D * MPAD];   // H transposed [d][node]
__device__ __nv_bfloat16 g_Htl[D * MPAD];
__device__ __nv_bfloat16 g_aSh[NS * KPAD2]; // alpha (sample dst), K-major
__device__ __nv_bfloat16 g_aSl[NS * KPAD2];
__device__ __nv_bfloat16 g_aPh[128 * MPAD]; // alpha (proxy dst), K over all nodes, self on diag
__device__ __nv_bfloat16 g_aPl[128 * MPAD];

__device__ __forceinline__ float lrelu(float v) { return v > 0.f ? v : 0.2f * v; }

__device__ __forceinline__ uint32_t smem_u32(const void* p) {
    uint32_t a;
    asm("{ .reg .u64 t; cvta.to.shared.u64 t, %1; cvt.u32.u64 %0, t; }" : "=r"(a) : "l"(p));
    return a;
}
__device__ __forceinline__ void bsplit(float v, __nv_bfloat16& hi, __nv_bfloat16& lo) {
    hi = __float2bfloat16(v);
    lo = __float2bfloat16(v - __bfloat162float(hi));
}

// PDL: wait for predecessor's memory, then allow successors to schedule
#define PDL_WAIT()   asm volatile("griddepcontrol.wait;" ::: "memory")
#define PDL_LAUNCH() asm volatile("griddepcontrol.launch_dependents;" ::: "memory")

// ============================ setup: W splits + input convert ============================
__global__ void k_setup(const float* __restrict__ W1, const float* __restrict__ W2,
                        const float* __restrict__ fcw,
                        const float* __restrict__ x, const float* __restrict__ prox) {
    PDL_LAUNCH();
    int b = blockIdx.x;
    if (b < 512) {
        const float* W = (b >= 256) ? W2 : W1;
        __nv_bfloat16* Wh = (b >= 256) ? g_W2h : g_W1h;
        __nv_bfloat16* Wl = (b >= 256) ? g_W2l : g_W1l;
        int bb = b & 255;
        __shared__ float t[32][33];
        int tx = threadIdx.x & 31, ty = threadIdx.x >> 5;
        int n0 = (bb & 15) * 32, k0 = (bb >> 4) * 32;
        #pragma unroll
        for (int j = 0; j < 4; j++)
            t[ty + 8 * j][tx] = W[(size_t)(k0 + ty + 8 * j) * D + n0 + tx];
        __syncthreads();
        #pragma unroll
        for (int j = 0; j < 4; j++) {
            int n = n0 + ty + 8 * j, k = k0 + tx;
            __nv_bfloat16 hi, lo;
            bsplit(t[tx][ty + 8 * j], hi, lo);
            Wh[(size_t)n * D + k] = hi;
            Wl[(size_t)n * D + k] = lo;
        }
    } else if (b < 576) {
        int bb = b - 512;
        __shared__ float t[32][33];
        int tx = threadIdx.x & 31, ty = threadIdx.x >> 5;
        int n0 = (bb & 3) * 32, k0 = (bb >> 2) * 32;
        #pragma unroll
        for (int j = 0; j < 4; j++) {
            int n = n0 + tx;
            t[ty + 8 * j][tx] = (n < 100) ? fcw[(size_t)(k0 + ty + 8 * j) * 100 + n] : 0.f;
        }
        __syncthreads();
        #pragma unroll
        for (int j = 0; j < 4; j++) {
            int n = n0 + ty + 8 * j, k = k0 + tx;
            __nv_bfloat16 hi, lo;
            bsplit(t[tx][ty + 8 * j], hi, lo);
            g_FCh[(size_t)n * D + k] = hi;
            g_FCl[(size_t)n * D + k] = lo;
        }
    } else {
        int row = (b - 576) * 2 + (threadIdx.x >> 7);
        int c4 = (threadIdx.x & 127) * 4;
        int base = row * D + c4;
        float4 v = make_float4(0.f, 0.f, 0.f, 0.f);
        if (row < NP)      v = *reinterpret_cast<const float4*>(prox + base);
        else if (row < NN) v = *reinterpret_cast<const float4*>(x + base - NP * D);
        __nv_bfloat16 h0, h1, h2, h3, l0, l1, l2, l3;
        bsplit(v.x, h0, l0); bsplit(v.y, h1, l1); bsplit(v.z, h2, l2); bsplit(v.w, h3, l3);
        *reinterpret_cast<__nv_bfloat162*>(g_Ah + base)     = __nv_bfloat162(h0, h1);
        *reinterpret_cast<__nv_bfloat162*>(g_Ah + base + 2) = __nv_bfloat162(h2, h3);
        *reinterpret_cast<__nv_bfloat162*>(g_Al + base)     = __nv_bfloat162(l0, l1);
        *reinterpret_cast<__nv_bfloat162*>(g_Al + base + 2) = __nv_bfloat162(l2, l3);
    }
}

// ============================ mma common ============================
#define SWB(r, b) ((r) * 128 + ((b) ^ (((r) & 7) << 4)))
#define STAGE_BYTES 32768
#define AGG_SMEM (2 * STAGE_BYTES + 16384)   // + fp32 self tile

__device__ __forceinline__ void ldm_x4(uint32_t* f, uint32_t addr) {
    asm volatile("ldmatrix.sync.aligned.m8n8.x4.shared.b16 {%0,%1,%2,%3}, [%4];"
                 : "=r"(f[0]), "=r"(f[1]), "=r"(f[2]), "=r"(f[3]) : "r"(addr));
}
__device__ __forceinline__ void ldm_x2(uint32_t* f, uint32_t addr) {
    asm volatile("ldmatrix.sync.aligned.m8n8.x2.shared.b16 {%0,%1}, [%2];"
                 : "=r"(f[0]), "=r"(f[1]) : "r"(addr));
}
__device__ __forceinline__ void mma_bf16(float* c, const uint32_t* a, const uint32_t* b) {
    asm volatile(
        "mma.sync.aligned.m16n8k16.row.col.f32.bf16.bf16.f32 "
        "{%0,%1,%2,%3}, {%4,%5,%6,%7}, {%8,%9}, {%0,%1,%2,%3};"
        : "+f"(c[0]), "+f"(c[1]), "+f"(c[2]), "+f"(c[3])
        : "r"(a[0]), "r"(a[1]), "r"(a[2]), "r"(a[3]), "r"(b[0]), "r"(b[1]));
}
__device__ __forceinline__ void cpa16(uint32_t saddr, const void* g) {
    asm volatile("cp.async.cg.shared.global [%0], [%1], 16;" :: "r"(saddr), "l"(g));
}

#define MMA_MAINLOOP(AH, AL, BH, BL, LDA, LDB, NCHUNK, KOFF)                             \
    int li = tid * 2;                                                                    \
    int lr0 = li >> 3, ls0 = li & 7;                                                     \
    int lr1 = (li + 1) >> 3, ls1 = (li + 1) & 7;                                         \
    int a_r = (lane & 7) + ((lane >> 3) & 1) * 8;                                        \
    int a_kb = (lane >> 4) * 16;                                                         \
    int b_r = lane & 7;                                                                  \
    int b_kb = ((lane >> 3) & 1) * 16;                                                   \
    float acc[2][2][4] = {};                                                             \
    auto issue = [&](int c, int st) {                                                    \
        int kc = (KOFF) + c * 64;                                                        \
        uint32_t stb = sb + st * STAGE_BYTES;                                            \
        cpa16(stb + SWB(lr0, ls0 * 16), (AH) + (size_t)(m0 + lr0) * (LDA) + kc + ls0 * 8); \
        cpa16(stb + SWB(lr1, ls1 * 16), (AH) + (size_t)(m0 + lr1) * (LDA) + kc + ls1 * 8); \
        cpa16(stb + 8192 + SWB(lr0, ls0 * 16), (AL) + (size_t)(m0 + lr0) * (LDA) + kc + ls0 * 8); \
        cpa16(stb + 8192 + SWB(lr1, ls1 * 16), (AL) + (size_t)(m0 + lr1) * (LDA) + kc + ls1 * 8); \
        cpa16(stb + 16384 + SWB(lr0, ls0 * 16), (BH) + (size_t)(n0 + lr0) * (LDB) + kc + ls0 * 8); \
        cpa16(stb + 16384 + SWB(lr1, ls1 * 16), (BH) + (size_t)(n0 + lr1) * (LDB) + kc + ls1 * 8); \
        cpa16(stb + 24576 + SWB(lr0, ls0 * 16), (BL) + (size_t)(n0 + lr0) * (LDB) + kc + ls0 * 8); \
        cpa16(stb + 24576 + SWB(lr1, ls1 * 16), (BL) + (size_t)(n0 + lr1) * (LDB) + kc + ls1 * 8); \
        asm volatile("cp.async.commit_group;");                                          \
    };                                                                                   \
    issue(0, 0);                                                                         \
    asm volatile("cp.async.wait_group 0;");                                              \
    __syncthreads();                                                                     \
    for (int c = 0; c < (NCHUNK); c++) {                                                 \
        int st = c & 1;                                                                  \
        if (c + 1 < (NCHUNK)) issue(c + 1, st ^ 1);                                      \
        uint32_t stb = sb + st * STAGE_BYTES;                                            \
        _Pragma("unroll")                                                                \
        for (int ks = 0; ks < 4; ks++) {                                                 \
            int kb = ks * 32;                                                            \
            uint32_t ah[2][4], al[2][4], bh[2][2], bl[2][2];                             \
            _Pragma("unroll")                                                            \
            for (int mt = 0; mt < 2; mt++) {                                             \
                int r = wm + mt * 16 + a_r;                                              \
                ldm_x4(ah[mt], stb + 0    + SWB(r, kb + a_kb));                          \
                ldm_x4(al[mt], stb + 8192 + SWB(r, kb + a_kb));                          \
            }                                                                            \
            _Pragma("unroll")                                                            \
            for (int nt = 0; nt < 2; nt++) {                                             \
                int r = wn + nt * 8 + b_r;                                               \
                ldm_x2(bh[nt], stb + 16384 + SWB(r, kb + b_kb));                         \
                ldm_x2(bl[nt], stb + 24576 + SWB(r, kb + b_kb));                         \
            }                                                                            \
            _Pragma("unroll")                                                            \
            for (int mt = 0; mt < 2; mt++)                                               \
                _Pragma("unroll")                                                        \
                for (int nt = 0; nt < 2; nt++) {                                         \
                    mma_bf16(acc[mt][nt], ah[mt], bh[nt]);                               \
                    mma_bf16(acc[mt][nt], ah[mt], bl[nt]);                               \
                    mma_bf16(acc[mt][nt], al[mt], bh[nt]);                               \
                }                                                                        \
        }                                                                                \
        if (c + 1 < (NCHUNK)) asm volatile("cp.async.wait_group 0;");                    \
        __syncthreads();                                                                 \
    }

// ============================ layer GEMM / FC GEMM ============================
__global__ void __launch_bounds__(256, 2) k_mma(
    const __nv_bfloat16* __restrict__ Ah, const __nv_bfloat16* __restrict__ Al,
    const __nv_bfloat16* __restrict__ Bh, const __nv_bfloat16* __restrict__ Bl,
    float* __restrict__ C, const float* __restrict__ bias, int mode,
    const float* __restrict__ asrc, const float* __restrict__ adst) {
    extern __shared__ __align__(16) char sm[];
    PDL_WAIT();
    PDL_LAUNCH();
    int tid = threadIdx.x, wid = tid >> 5, lane = tid & 31;
    int n0 = blockIdx.x * 64, m0 = blockIdx.y * 64;
    int wm = (wid >> 2) * 32, wn = (wid & 3) * 16;
    uint32_t sb = smem_u32(sm);

    MMA_MAINLOOP(Ah, Al, Bh, Bl, D, D, 8, 0)

    if (mode == 0) {
        #pragma unroll
        for (int mt = 0; mt < 2; mt++) {
            int row = m0 + wm + mt * 16 + (lane >> 2);
            #pragma unroll
            for (int nt = 0; nt < 2; nt++) {
                int col = n0 + wn + nt * 8 + (lane & 3) * 2;
                if (col >= 100) continue;
                float b0 = bias[col], b1 = bias[col + 1];
                *reinterpret_cast<float2*>(C + (size_t)row * 100 + col) =
                    make_float2(acc[mt][nt][0] + b0, acc[mt][nt][1] + b1);
                *reinterpret_cast<float2*>(C + (size_t)(row + 8) * 100 + col) =
                    make_float2(acc[mt][nt][2] + b0, acc[mt][nt][3] + b1);
            }
        }
        return;
    }

    // fp32 HW store
    #pragma unroll
    for (int mt = 0; mt < 2; mt++) {
        int row = m0 + wm + mt * 16 + (lane >> 2);
        #pragma unroll
        for (int nt = 0; nt < 2; nt++) {
            int col = n0 + wn + nt * 8 + (lane & 3) * 2;
            *reinterpret_cast<float2*>(g_HW + (size_t)row * D + col) =
                make_float2(acc[mt][nt][0], acc[mt][nt][1]);
            *reinterpret_cast<float2*>(g_HW + (size_t)(row + 8) * D + col) =
                make_float2(acc[mt][nt][2], acc[mt][nt][3]);
        }
    }

    // logit partials
    {
        float* lpb = reinterpret_cast<float*>(sm);   // [64][4][2]
        #pragma unroll
        for (int mt = 0; mt < 2; mt++)
            #pragma unroll
            for (int half = 0; half < 2; half++) {
                int rl = wm + mt * 16 + (lane >> 2) + half * 8;
                float s = 0.f, t = 0.f;
                #pragma unroll
                for (int nt = 0; nt < 2; nt++) {
                    int col = n0 + wn + nt * 8 + (lane & 3) * 2;
                    float v0 = acc[mt][nt][half * 2], v1 = acc[mt][nt][half * 2 + 1];
                    s += v0 * asrc[col] + v1 * asrc[col + 1];
                    t += v0 * adst[col] + v1 * adst[col + 1];
                }
                s += __shfl_xor_sync(0xffffffffu, s, 1);
                s += __shfl_xor_sync(0xffffffffu, s, 2);
                t += __shfl_xor_sync(0xffffffffu, t, 1);
                t += __shfl_xor_sync(0xffffffffu, t, 2);
                if ((lane & 3) == 0) {
                    lpb[(rl * 4 + (wid & 3)) * 2 + 0] = s;
                    lpb[(rl * 4 + (wid & 3)) * 2 + 1] = t;
                }
            }
        __syncthreads();
        if (tid < 128) {
            int rl = tid >> 1, comp = tid & 1;
            int row = m0 + rl;
            if (row < NN) {
                float s = lpb[(rl * 4 + 0) * 2 + comp] + lpb[(rl * 4 + 1) * 2 + comp]
                        + lpb[(rl * 4 + 2) * 2 + comp] + lpb[(rl * 4 + 3) * 2 + comp];
                g_lp[n0 >> 6][row][comp] = s;
            }
        }
        __syncthreads();
    }

    // transpose via smem, write Ht bf16 split
    float* ts = reinterpret_cast<float*>(sm);   // [64][65]
    #pragma unroll
    for (int mt = 0; mt < 2; mt++)
        #pragma unroll
        for (int nt = 0; nt < 2; nt++)
            #pragma unroll
            for (int j = 0; j < 4; j++) {
                int rl = wm + mt * 16 + (lane >> 2) + (j >> 1) * 8;
                int cl = wn + nt * 8 + (lane & 3) * 2 + (j & 1);
                ts[rl * 65 + cl] = acc[mt][nt][j];
            }
    __syncthreads();
    #pragma unroll
    for (int it = 0; it < 16; it++) {
        int lin = it * 256 + tid;
        int n = lin >> 6, m = lin & 63;
        __nv_bfloat16 hi, lo;
        bsplit(ts[m * 65 + n], hi, lo);
        g_Hth[(size_t)(n0 + n) * MPAD + m0 + m] = hi;
        g_Htl[(size_t)(n0 + n) * MPAD + m0 + m] = lo;
    }
}

// ============================ alpha (from g_lp; no max subtraction) ============================
__global__ void k_alpha(int layer) {
    PDL_WAIT();
    PDL_LAUNCH();
    int tid = threadIdx.x;
    int b = blockIdx.x;
    if (b < 128) {
        __shared__ float lsp[128];
        if (tid < NP) {
            float s = 0.f;
            #pragma unroll
            for (int ti = 0; ti < 8; ti++)
                s += reinterpret_cast<const float2*>(&g_lp[ti][tid][0])->x;
            lsp[tid] = s;
        }
        __syncthreads();
        int warp = b * 8 + (tid >> 5);
        int lane = tid & 31;
        int node = NP + warp;
        float lsn = 0.f, ldn = 0.f;
        #pragma unroll
        for (int ti = 0; ti < 8; ti++) {
            float2 v = *reinterpret_cast<const float2*>(&g_lp[ti][node][0]);
            lsn += v.x;
            ldn += v.y;
        }
        float w[4], sum = 0.f;
        #pragma unroll
        for (int i = 0; i < 4; i++) {
            int p = lane + 32 * i;
            w[i] = (p < NP) ? __expf(lrelu(lsp[p] + ldn)) : 0.f;
            sum += w[i];
        }
        float wself = __expf(lrelu(lsn + ldn));
        #pragma unroll
        for (int o = 16; o > 0; o >>= 1) sum += __shfl_xor_sync(0xffffffffu, sum, o);
        float inv = 1.f / (sum + wself);
        #pragma unroll
        for (int i = 0; i < 4; i++) {
            int p = lane + 32 * i;
            __nv_bfloat16 hi, lo;
            bsplit(w[i] * inv, hi, lo);
            g_aSh[(size_t)warp * KPAD2 + p] = hi;
            g_aSl[(size_t)warp * KPAD2 + p] = lo;
        }
        if (lane == 0) g_aselfS[warp] = wself * inv;
    } else if (b < 228) {
        __shared__ float sh[8];
        __shared__ float s_inv;
        int p = b - 128;
        float ldp = 0.f, lspp = 0.f;
        #pragma unroll
        for (int ti = 0; ti < 8; ti++) {
            float2 v = *reinterpret_cast<const float2*>(&g_lp[ti][p][0]);
            lspp += v.x;
            ldp += v.y;
        }
        float w[4], sum = 0.f;
        #pragma unroll
        for (int i = 0; i < 4; i++) {
            int s = tid + i * 256;
            float ls = 0.f;
            #pragma unroll
            for (int ti = 0; ti < 8; ti++)
                ls += reinterpret_cast<const float2*>(&g_lp[ti][NP + s][0])->x;
            w[i] = __expf(lrelu(ls + ldp));
            sum += w[i];
        }
        float wself = __expf(lrelu(lspp + ldp));
        #pragma unroll
        for (int o = 16; o > 0; o >>= 1) sum += __shfl_xor_sync(0xffffffffu, sum, o);
        if ((tid & 31) == 0) sh[tid >> 5] = sum;
        __syncthreads();
        if (tid == 0) {
            float ss = 0.f;
            #pragma unroll
            for (int i = 0; i < 8; i++) ss += sh[i];
            s_inv = 1.f / (ss + wself);
        }
        __syncthreads();
        float inv = s_inv;
        #pragma unroll
        for (int i = 0; i < 4; i++) {
            int col = NP + tid + i * 256;
            __nv_bfloat16 hi, lo;
            bsplit(w[i] * inv, hi, lo);
            g_aPh[(size_t)p * MPAD + col] = hi;
            g_aPl[(size_t)p * MPAD + col] = lo;
        }
        if (tid < NP) {
            float dv = (tid == p) ? wself * inv : 0.f;
            __nv_bfloat16 hi, lo;
            bsplit(dv, hi, lo);
            g_aPh[(size_t)p * MPAD + tid] = hi;
            g_aPl[(size_t)p * MPAD + tid] = lo;
        }
        if (tid < MPAD - NN) {
            __nv_bfloat16 z = __float2bfloat16(0.f);
            g_aPh[(size_t)p * MPAD + NN + tid] = z;
            g_aPl[(size_t)p * MPAD + NN + tid] = z;
        }
    } else {
        int p = 100 + (b - 228);
        uint32_t* h = reinterpret_cast<uint32_t*>(g_aPh + (size_t)p * MPAD);
        uint32_t* l = reinterpret_cast<uint32_t*>(g_aPl + (size_t)p * MPAD);
        for (int i = tid; i < MPAD / 2; i += 256) { h[i] = 0u; l[i] = 0u; }
    }
}

// ============================ aggregation GEMM (tensor cores) ============================
__global__ void __launch_bounds__(256, 2) k_aggm(const float* __restrict__ bias,
                                                 float* __restrict__ hout, int layer) {
    extern __shared__ __align__(16) char sm[];
    PDL_WAIT();
    PDL_LAUNCH();
    int tid = threadIdx.x, wid = tid >> 5, lane = tid & 31;
    int wm = (wid >> 2) * 32, wn = (wid & 3) * 16;
    uint32_t sb = smem_u32(sm);
    int b = blockIdx.x;

    if (b < 128) {
        int m0 = (b >> 3) * 64, n0 = (b & 7) * 64;

        // prefetch fp32 self tile (covered by the mainloop's wait_group 0)
        #pragma unroll
        for (int q = 0; q < 4; q++) {
            int i = tid + q * 256;
            int r = i >> 4, cc = (i & 15) * 4;
            cpa16(sb + 65536 + i * 16, g_HW + (size_t)(NP + m0 + r) * D + n0 + cc);
        }
        asm volatile("cp.async.commit_group;");

        MMA_MAINLOOP(g_aSh, g_aSl, g_Hth, g_Htl, KPAD2, MPAD, 2, 0)

        const float* selfS = reinterpret_cast<const float*>(sm + 65536);
        #pragma unroll
        for (int mt = 0; mt < 2; mt++)
            #pragma unroll
            for (int nt = 0; nt < 2; nt++)
                #pragma unroll
                for (int j = 0; j < 4; j++) {
                    int rl = wm + mt * 16 + (lane >> 2) + (j >> 1) * 8;
                    int cl = wn + nt * 8 + (lane & 3) * 2 + (j & 1);
                    float v = acc[mt][nt][j] + g_aselfS[m0 + rl] * selfS[rl * 64 + cl]
                            + bias[n0 + cl];
                    acc[mt][nt][j] = v > 0.f ? v : 0.f;
                }
        #pragma unroll
        for (int mt = 0; mt < 2; mt++)
            #pragma unroll
            for (int half = 0; half < 2; half++) {
                int r = m0 + wm + mt * 16 + (lane >> 2) + half * 8;
                int arow = (layer == 1) ? (NP + r) : r;
                #pragma unroll
                for (int nt = 0; nt < 2; nt++) {
                    int col = n0 + wn + nt * 8 + (lane & 3) * 2;
                    float v0 = acc[mt][nt][half * 2], v1 = acc[mt][nt][half * 2 + 1];
                    __nv_bfloat16 h0, h1, l0, l1;
                    bsplit(v0, h0, l0); bsplit(v1, h1, l1);
                    *reinterpret_cast<__nv_bfloat162*>(g_Ah + (size_t)arow * D + col) =
                        __nv_bfloat162(h0, h1);
                    *reinterpret_cast<__nv_bfloat162*>(g_Al + (size_t)arow * D + col) =
                        __nv_bfloat162(l0, l1);
                    if (layer == 2)
                        *reinterpret_cast<float2*>(hout + (size_t)r * D + col) =
                            make_float2(v0, v1);
                }
            }
    } else {
        int bb = b - 128;
        int tile = bb & 15;
        int z = bb >> 4;                       // split index 0..8
        int m0 = (tile >> 3) * 64, n0 = (tile & 7) * 64;
        MMA_MAINLOOP(g_aPh, g_aPl, g_Hth, g_Htl, MPAD, MPAD, 2, z * 128)
        float* part = &g_ppart[z][0][0];
        #pragma unroll
        for (int mt = 0; mt < 2; mt++)
            #pragma unroll
            for (int half = 0; half < 2; half++) {
                int p = m0 + wm + mt * 16 + (lane >> 2) + half * 8;
                if (p >= NP) continue;
                #pragma unroll
                for (int nt = 0; nt < 2; nt++) {
                    int col = n0 + wn + nt * 8 + (lane & 3) * 2;
                    *reinterpret_cast<float2*>(part + (size_t)p * D + col) =
                        make_float2(acc[mt][nt][half * 2], acc[mt][nt][half * 2 + 1]);
                }
            }
    }
}

// proxy finalize: sum 9 split-K partials + bias, relu -> bf16 split rows 0..99 of g_Ah/g_Al
__global__ void k_pfin(const float* __restrict__ bias) {
    PDL_WAIT();
    PDL_LAUNCH();
    int idx = blockIdx.x * 256 + threadIdx.x;
    int p = idx / (D / 2);
    int c = (idx - p * (D / 2)) * 2;
    float v0 = 0.f, v1 = 0.f;
    #pragma unroll
    for (int z = 0; z < PSPLIT; z++) {
        float2 t = *reinterpret_cast<const float2*>(&g_ppart[z][p][c]);
        v0 += t.x; v1 += t.y;
    }
    v0 += bias[c];     v0 = v0 > 0.f ? v0 : 0.f;
    v1 += bias[c + 1]; v1 = v1 > 0.f ? v1 : 0.f;
    __nv_bfloat16 h0, h1, l0, l1;
    bsplit(v0, h0, l0); bsplit(v1, h1, l1);
    *reinterpret_cast<__nv_bfloat162*>(g_Ah + (size_t)p * D + c) = __nv_bfloat162(h0, h1);
    *reinterpret_cast<__nv_bfloat162*>(g_Al + (size_t)p * D + c) = __nv_bfloat162(l0, l1);
}

// ============================ launch ============================
template <typename... Args>
static inline void launch_pdl(void (*kern)(Args...), dim3 grid, dim3 block, size_t smem,
                              Args... args) {
    cudaLaunchConfig_t cfg = {};
    cfg.gridDim = grid;
    cfg.blockDim = block;
    cfg.dynamicSmemBytes = smem;
    cfg.stream = 0;
    cudaLaunchAttribute at[1];
    at[0].id = cudaLaunchAttributeProgrammaticStreamSerialization;
    at[0].val.programmaticStreamSerializationAllowed = 1;
    cfg.attrs = at;
    cfg.numAttrs = 1;
    cudaLaunchKernelEx(&cfg, kern, args...);
}

extern "C" void kernel_launch(void* const* d_in, const int* in_sizes, int n_in,
                              void* d_out, int out_size) {
    const float* x    = (const float*)d_in[0];
    const float* prox = (const float*)d_in[1];
    const float* W1   = (const float*)d_in[2];
    const float* as1  = (const float*)d_in[3];
    const float* ad1  = (const float*)d_in[4];
    const float* b1   = (const float*)d_in[5];
    const float* W2   = (const float*)d_in[6];
    const float* as2  = (const float*)d_in[7];
    const float* ad2  = (const float*)d_in[8];
    const float* b2   = (const float*)d_in[9];
    const float* fcw  = (const float*)d_in[10];
    const float* fcb  = (const float*)d_in[11];
    float* out = (float*)d_out;

    __nv_bfloat16 *pAh, *pAl, *pW1h, *pW1l, *pW2h, *pW2l, *pFCh, *pFCl;
    cudaGetSymbolAddress((void**)&pAh,  g_Ah);
    cudaGetSymbolAddress((void**)&pAl,  g_Al);
    cudaGetSymbolAddress((void**)&pW1h, g_W1h);
    cudaGetSymbolAddress((void**)&pW1l, g_W1l);
    cudaGetSymbolAddress((void**)&pW2h, g_W2h);
    cudaGetSymbolAddress((void**)&pW2l, g_W2l);
    cudaGetSymbolAddress((void**)&pFCh, g_FCh);
    cudaGetSymbolAddress((void**)&pFCl, g_FCl);

    cudaFuncSetAttribute(k_mma,  cudaFuncAttributeMaxDynamicSharedMemorySize, 2 * STAGE_BYTES);
    cudaFuncSetAttribute(k_aggm, cudaFuncAttributeMaxDynamicSharedMemorySize, AGG_SMEM);

    k_setup<<<1152, 256>>>(W1, W2, fcw, x, prox);

    // ---- layer 1
    launch_pdl(k_mma, dim3(8, 18), dim3(256), (size_t)(2 * STAGE_BYTES),
               (const __nv_bfloat16*)pAh, (const __nv_bfloat16*)pAl,
               (const __nv_bfloat16*)pW1h, (const __nv_bfloat16*)pW1l,
               (float*)nullptr, (const float*)nullptr, 1, as1, ad1);
    launch_pdl(k_alpha, dim3(256), dim3(256), (size_t)0, 1);
    launch_pdl(k_aggm, dim3(128 + 16 * PSPLIT), dim3(256), (size_t)AGG_SMEM,
               b1, (float*)nullptr, 1);
    launch_pdl(k_pfin, dim3(NP * D / 512), dim3(256), (size_t)0, b1);

    // ---- layer 2 (proxy aggregation unused downstream)
    launch_pdl(k_mma, dim3(8, 18), dim3(256), (size_t)(2 * STAGE_BYTES),
               (const __nv_bfloat16*)pAh, (const __nv_bfloat16*)pAl,
               (const __nv_bfloat16*)pW2h, (const __nv_bfloat16*)pW2l,
               (float*)nullptr, (const float*)nullptr, 1, as2, ad2);
    launch_pdl(k_alpha, dim3(128), dim3(256), (size_t)0, 2);
    launch_pdl(k_aggm, dim3(128), dim3(256), (size_t)AGG_SMEM,
               b2, out + NS * 100, 2);

    // ---- preds = h @ fc_w + fc_b
    launch_pdl(k_mma, dim3(2, 16), dim3(256), (size_t)(2 * STAGE_BYTES),
               (const __nv_bfloat16*)pAh, (const __nv_bfloat16*)pAl,
               (const __nv_bfloat16*)pFCh, (const __nv_bfloat16*)pFCl,
               out, fcb, 0, (const float*)nullptr, (const float*)nullptr);
}

// round 16
// speedup vs baseline: 1.4038x; 1.0291x over previous
#include <cuda_runtime.h>
#include <cuda_bf16.h>
#include <cstdint>

#define NP 100      // proxies
#define NS 1024     // samples
#define NN 1124     // total nodes
#define MPAD 1152   // NN padded to 128
#define D  512
#define KPAD2 128   // NP padded for sample-agg K
#define PSPLIT 9    // proxy-agg split-K factor (9 x 128 = 1152)

// scratch (device globals; no allocation allowed)
__device__ float g_HW[MPAD * D];
__device__ float g_aselfS[NS];
__device__ float g_lp[8][NN][2];        // logit partials [64col-tile][node][src/dst]
__device__ float g_ppart[PSPLIT][128][D];
__device__ unsigned g_cntP[16];         // split-K arrival counters (self-resetting)
// bf16 split operands
__device__ __nv_bfloat16 g_Ah[MPAD * D];
__device__ __nv_bfloat16 g_Al[MPAD * D];
__device__ __nv_bfloat16 g_W1h[D * D];
__device__ __nv_bfloat16 g_W1l[D * D];
__device__ __nv_bfloat16 g_W2h[D * D];
__device__ __nv_bfloat16 g_W2l[D * D];
__device__ __nv_bfloat16 g_FCh[128 * D];
__device__ __nv_bfloat16 g_FCl[128 * D];
__device__ __nv_bfloat16 g_Hth[D * MPAD];   // H transposed [d][node]
__device__ __nv_bfloat16 g_Htl[D * MPAD];
__device__ __nv_bfloat16 g_aSh[NS * KPAD2]; // alpha (sample dst), K-major
__device__ __nv_bfloat16 g_aSl[NS * KPAD2];
__device__ __nv_bfloat16 g_aPh[128 * MPAD]; // alpha (proxy dst), K over all nodes, self on diag
__device__ __nv_bfloat16 g_aPl[128 * MPAD];

__device__ __forceinline__ float lrelu(float v) { return v > 0.f ? v : 0.2f * v; }

__device__ __forceinline__ uint32_t smem_u32(const void* p) {
    uint32_t a;
    asm("{ .reg .u64 t; cvta.to.shared.u64 t, %1; cvt.u32.u64 %0, t; }" : "=r"(a) : "l"(p));
    return a;
}
__device__ __forceinline__ void bsplit(float v, __nv_bfloat16& hi, __nv_bfloat16& lo) {
    hi = __float2bfloat16(v);
    lo = __float2bfloat16(v - __bfloat162float(hi));
}

// ============================ setup: W splits + input convert ============================
__global__ void k_setup(const float* __restrict__ W1, const float* __restrict__ W2,
                        const float* __restrict__ fcw,
                        const float* __restrict__ x, const float* __restrict__ prox) {
    int b = blockIdx.x;
    if (b < 512) {
        const float* W = (b >= 256) ? W2 : W1;
        __nv_bfloat16* Wh = (b >= 256) ? g_W2h : g_W1h;
        __nv_bfloat16* Wl = (b >= 256) ? g_W2l : g_W1l;
        int bb = b & 255;
        __shared__ float t[32][33];
        int tx = threadIdx.x & 31, ty = threadIdx.x >> 5;
        int n0 = (bb & 15) * 32, k0 = (bb >> 4) * 32;
        #pragma unroll
        for (int j = 0; j < 4; j++)
            t[ty + 8 * j][tx] = W[(size_t)(k0 + ty + 8 * j) * D + n0 + tx];
        __syncthreads();
        #pragma unroll
        for (int j = 0; j < 4; j++) {
            int n = n0 + ty + 8 * j, k = k0 + tx;
            __nv_bfloat16 hi, lo;
            bsplit(t[tx][ty + 8 * j], hi, lo);
            Wh[(size_t)n * D + k] = hi;
            Wl[(size_t)n * D + k] = lo;
        }
    } else if (b < 576) {
        int bb = b - 512;
        __shared__ float t[32][33];
        int tx = threadIdx.x & 31, ty = threadIdx.x >> 5;
        int n0 = (bb & 3) * 32, k0 = (bb >> 2) * 32;
        #pragma unroll
        for (int j = 0; j < 4; j++) {
            int n = n0 + tx;
            t[ty + 8 * j][tx] = (n < 100) ? fcw[(size_t)(k0 + ty + 8 * j) * 100 + n] : 0.f;
        }
        __syncthreads();
        #pragma unroll
        for (int j = 0; j < 4; j++) {
            int n = n0 + ty + 8 * j, k = k0 + tx;
            __nv_bfloat16 hi, lo;
            bsplit(t[tx][ty + 8 * j], hi, lo);
            g_FCh[(size_t)n * D + k] = hi;
            g_FCl[(size_t)n * D + k] = lo;
        }
    } else {
        int row = (b - 576) * 2 + (threadIdx.x >> 7);
        int c4 = (threadIdx.x & 127) * 4;
        int base = row * D + c4;
        float4 v = make_float4(0.f, 0.f, 0.f, 0.f);
        if (row < NP)      v = *reinterpret_cast<const float4*>(prox + base);
        else if (row < NN) v = *reinterpret_cast<const float4*>(x + base - NP * D);
        __nv_bfloat16 h0, h1, h2, h3, l0, l1, l2, l3;
        bsplit(v.x, h0, l0); bsplit(v.y, h1, l1); bsplit(v.z, h2, l2); bsplit(v.w, h3, l3);
        *reinterpret_cast<__nv_bfloat162*>(g_Ah + base)     = __nv_bfloat162(h0, h1);
        *reinterpret_cast<__nv_bfloat162*>(g_Ah + base + 2) = __nv_bfloat162(h2, h3);
        *reinterpret_cast<__nv_bfloat162*>(g_Al + base)     = __nv_bfloat162(l0, l1);
        *reinterpret_cast<__nv_bfloat162*>(g_Al + base + 2) = __nv_bfloat162(l2, l3);
    }
}

// ============================ mma common ============================
#define SWB(r, b) ((r) * 128 + ((b) ^ (((r) & 7) << 4)))
#define STAGE_BYTES 32768
#define AGG_SMEM (2 * STAGE_BYTES + 16384)   // + fp32 self tile

__device__ __forceinline__ void ldm_x4(uint32_t* f, uint32_t addr) {
    asm volatile("ldmatrix.sync.aligned.m8n8.x4.shared.b16 {%0,%1,%2,%3}, [%4];"
                 : "=r"(f[0]), "=r"(f[1]), "=r"(f[2]), "=r"(f[3]) : "r"(addr));
}
__device__ __forceinline__ void ldm_x2(uint32_t* f, uint32_t addr) {
    asm volatile("ldmatrix.sync.aligned.m8n8.x2.shared.b16 {%0,%1}, [%2];"
                 : "=r"(f[0]), "=r"(f[1]) : "r"(addr));
}
__device__ __forceinline__ void mma_bf16(float* c, const uint32_t* a, const uint32_t* b) {
    asm volatile(
        "mma.sync.aligned.m16n8k16.row.col.f32.bf16.bf16.f32 "
        "{%0,%1,%2,%3}, {%4,%5,%6,%7}, {%8,%9}, {%0,%1,%2,%3};"
        : "+f"(c[0]), "+f"(c[1]), "+f"(c[2]), "+f"(c[3])
        : "r"(a[0]), "r"(a[1]), "r"(a[2]), "r"(a[3]), "r"(b[0]), "r"(b[1]));
}
__device__ __forceinline__ void cpa16(uint32_t saddr, const void* g) {
    asm volatile("cp.async.cg.shared.global [%0], [%1], 16;" :: "r"(saddr), "l"(g));
}

#define MMA_MAINLOOP(AH, AL, BH, BL, LDA, LDB, NCHUNK, KOFF)                             \
    int li = tid * 2;                                                                    \
    int lr0 = li >> 3, ls0 = li & 7;                                                     \
    int lr1 = (li + 1) >> 3, ls1 = (li + 1) & 7;                                         \
    int a_r = (lane & 7) + ((lane >> 3) & 1) * 8;                                        \
    int a_kb = (lane >> 4) * 16;                                                         \
    int b_r = lane & 7;                                                                  \
    int b_kb = ((lane >> 3) & 1) * 16;                                                   \
    float acc[2][2][4] = {};                                                             \
    auto issue = [&](int c, int st) {                                                    \
        int kc = (KOFF) + c * 64;                                                        \
        uint32_t stb = sb + st * STAGE_BYTES;                                            \
        cpa16(stb + SWB(lr0, ls0 * 16), (AH) + (size_t)(m0 + lr0) * (LDA) + kc + ls0 * 8); \
        cpa16(stb + SWB(lr1, ls1 * 16), (AH) + (size_t)(m0 + lr1) * (LDA) + kc + ls1 * 8); \
        cpa16(stb + 8192 + SWB(lr0, ls0 * 16), (AL) + (size_t)(m0 + lr0) * (LDA) + kc + ls0 * 8); \
        cpa16(stb + 8192 + SWB(lr1, ls1 * 16), (AL) + (size_t)(m0 + lr1) * (LDA) + kc + ls1 * 8); \
        cpa16(stb + 16384 + SWB(lr0, ls0 * 16), (BH) + (size_t)(n0 + lr0) * (LDB) + kc + ls0 * 8); \
        cpa16(stb + 16384 + SWB(lr1, ls1 * 16), (BH) + (size_t)(n0 + lr1) * (LDB) + kc + ls1 * 8); \
        cpa16(stb + 24576 + SWB(lr0, ls0 * 16), (BL) + (size_t)(n0 + lr0) * (LDB) + kc + ls0 * 8); \
        cpa16(stb + 24576 + SWB(lr1, ls1 * 16), (BL) + (size_t)(n0 + lr1) * (LDB) + kc + ls1 * 8); \
        asm volatile("cp.async.commit_group;");                                          \
    };                                                                                   \
    issue(0, 0);                                                                         \
    asm volatile("cp.async.wait_group 0;");                                              \
    __syncthreads();                                                                     \
    for (int c = 0; c < (NCHUNK); c++) {                                                 \
        int st = c & 1;                                                                  \
        if (c + 1 < (NCHUNK)) issue(c + 1, st ^ 1);                                      \
        uint32_t stb = sb + st * STAGE_BYTES;                                            \
        _Pragma("unroll")                                                                \
        for (int ks = 0; ks < 4; ks++) {                                                 \
            int kb = ks * 32;                                                            \
            uint32_t ah[2][4], al[2][4], bh[2][2], bl[2][2];                             \
            _Pragma("unroll")                                                            \
            for (int mt = 0; mt < 2; mt++) {                                             \
                int r = wm + mt * 16 + a_r;                                              \
                ldm_x4(ah[mt], stb + 0    + SWB(r, kb + a_kb));                          \
                ldm_x4(al[mt], stb + 8192 + SWB(r, kb + a_kb));                          \
            }                                                                            \
            _Pragma("unroll")                                                            \
            for (int nt = 0; nt < 2; nt++) {                                             \
                int r = wn + nt * 8 + b_r;                                               \
                ldm_x2(bh[nt], stb + 16384 + SWB(r, kb + b_kb));                         \
                ldm_x2(bl[nt], stb + 24576 + SWB(r, kb + b_kb));                         \
            }                                                                            \
            _Pragma("unroll")                                                            \
            for (int mt = 0; mt < 2; mt++)                                               \
                _Pragma("unroll")                                                        \
                for (int nt = 0; nt < 2; nt++) {                                         \
                    mma_bf16(acc[mt][nt], ah[mt], bh[nt]);                               \
                    mma_bf16(acc[mt][nt], ah[mt], bl[nt]);                               \
                    mma_bf16(acc[mt][nt], al[mt], bh[nt]);                               \
                }                                                                        \
        }                                                                                \
        if (c + 1 < (NCHUNK)) asm volatile("cp.async.wait_group 0;");                    \
        __syncthreads();                                                                 \
    }

// ============================ layer GEMM / FC GEMM ============================
__global__ void __launch_bounds__(256, 2) k_mma(
    const __nv_bfloat16* __restrict__ Ah, const __nv_bfloat16* __restrict__ Al,
    const __nv_bfloat16* __restrict__ Bh, const __nv_bfloat16* __restrict__ Bl,
    float* __restrict__ C, const float* __restrict__ bias, int mode,
    const float* __restrict__ asrc, const float* __restrict__ adst) {
    extern __shared__ __align__(16) char sm[];
    int tid = threadIdx.x, wid = tid >> 5, lane = tid & 31;
    int n0 = blockIdx.x * 64, m0 = blockIdx.y * 64;
    int wm = (wid >> 2) * 32, wn = (wid & 3) * 16;
    uint32_t sb = smem_u32(sm);

    MMA_MAINLOOP(Ah, Al, Bh, Bl, D, D, 8, 0)

    if (mode == 0) {
        #pragma unroll
        for (int mt = 0; mt < 2; mt++) {
            int row = m0 + wm + mt * 16 + (lane >> 2);
            #pragma unroll
            for (int nt = 0; nt < 2; nt++) {
                int col = n0 + wn + nt * 8 + (lane & 3) * 2;
                if (col >= 100) continue;
                float b0 = bias[col], b1 = bias[col + 1];
                *reinterpret_cast<float2*>(C + (size_t)row * 100 + col) =
                    make_float2(acc[mt][nt][0] + b0, acc[mt][nt][1] + b1);
                *reinterpret_cast<float2*>(C + (size_t)(row + 8) * 100 + col) =
                    make_float2(acc[mt][nt][2] + b0, acc[mt][nt][3] + b1);
            }
        }
        return;
    }

    // fp32 HW store
    #pragma unroll
    for (int mt = 0; mt < 2; mt++) {
        int row = m0 + wm + mt * 16 + (lane >> 2);
        #pragma unroll
        for (int nt = 0; nt < 2; nt++) {
            int col = n0 + wn + nt * 8 + (lane & 3) * 2;
            *reinterpret_cast<float2*>(g_HW + (size_t)row * D + col) =
                make_float2(acc[mt][nt][0], acc[mt][nt][1]);
            *reinterpret_cast<float2*>(g_HW + (size_t)(row + 8) * D + col) =
                make_float2(acc[mt][nt][2], acc[mt][nt][3]);
        }
    }

    // logit partials
    {
        float* lpb = reinterpret_cast<float*>(sm);   // [64][4][2]
        #pragma unroll
        for (int mt = 0; mt < 2; mt++)
            #pragma unroll
            for (int half = 0; half < 2; half++) {
                int rl = wm + mt * 16 + (lane >> 2) + half * 8;
                float s = 0.f, t = 0.f;
                #pragma unroll
                for (int nt = 0; nt < 2; nt++) {
                    int col = n0 + wn + nt * 8 + (lane & 3) * 2;
                    float v0 = acc[mt][nt][half * 2], v1 = acc[mt][nt][half * 2 + 1];
                    s += v0 * asrc[col] + v1 * asrc[col + 1];
                    t += v0 * adst[col] + v1 * adst[col + 1];
                }
                s += __shfl_xor_sync(0xffffffffu, s, 1);
                s += __shfl_xor_sync(0xffffffffu, s, 2);
                t += __shfl_xor_sync(0xffffffffu, t, 1);
                t += __shfl_xor_sync(0xffffffffu, t, 2);
                if ((lane & 3) == 0) {
                    lpb[(rl * 4 + (wid & 3)) * 2 + 0] = s;
                    lpb[(rl * 4 + (wid & 3)) * 2 + 1] = t;
                }
            }
        __syncthreads();
        if (tid < 128) {
            int rl = tid >> 1, comp = tid & 1;
            int row = m0 + rl;
            if (row < NN) {
                float s = lpb[(rl * 4 + 0) * 2 + comp] + lpb[(rl * 4 + 1) * 2 + comp]
                        + lpb[(rl * 4 + 2) * 2 + comp] + lpb[(rl * 4 + 3) * 2 + comp];
                g_lp[n0 >> 6][row][comp] = s;
            }
        }
        __syncthreads();
    }

    // transpose via smem, write Ht bf16 split
    float* ts = reinterpret_cast<float*>(sm);   // [64][65]
    #pragma unroll
    for (int mt = 0; mt < 2; mt++)
        #pragma unroll
        for (int nt = 0; nt < 2; nt++)
            #pragma unroll
            for (int j = 0; j < 4; j++) {
                int rl = wm + mt * 16 + (lane >> 2) + (j >> 1) * 8;
                int cl = wn + nt * 8 + (lane & 3) * 2 + (j & 1);
                ts[rl * 65 + cl] = acc[mt][nt][j];
            }
    __syncthreads();
    #pragma unroll
    for (int it = 0; it < 16; it++) {
        int lin = it * 256 + tid;
        int n = lin >> 6, m = lin & 63;
        __nv_bfloat16 hi, lo;
        bsplit(ts[m * 65 + n], hi, lo);
        g_Hth[(size_t)(n0 + n) * MPAD + m0 + m] = hi;
        g_Htl[(size_t)(n0 + n) * MPAD + m0 + m] = lo;
    }
}

// ============================ alpha (from g_lp; no max subtraction) ============================
__global__ void k_alpha(int layer) {
    int tid = threadIdx.x;
    int b = blockIdx.x;
    if (b < 128) {
        __shared__ float lsp[128];
        if (tid < NP) {
            float s = 0.f;
            #pragma unroll
            for (int ti = 0; ti < 8; ti++)
                s += reinterpret_cast<const float2*>(&g_lp[ti][tid][0])->x;
            lsp[tid] = s;
        }
        __syncthreads();
        int warp = b * 8 + (tid >> 5);
        int lane = tid & 31;
        int node = NP + warp;
        float lsn = 0.f, ldn = 0.f;
        #pragma unroll
        for (int ti = 0; ti < 8; ti++) {
            float2 v = *reinterpret_cast<const float2*>(&g_lp[ti][node][0]);
            lsn += v.x;
            ldn += v.y;
        }
        float w[4], sum = 0.f;
        #pragma unroll
        for (int i = 0; i < 4; i++) {
            int p = lane + 32 * i;
            w[i] = (p < NP) ? __expf(lrelu(lsp[p] + ldn)) : 0.f;
            sum += w[i];
        }
        float wself = __expf(lrelu(lsn + ldn));
        #pragma unroll
        for (int o = 16; o > 0; o >>= 1) sum += __shfl_xor_sync(0xffffffffu, sum, o);
        float inv = 1.f / (sum + wself);
        #pragma unroll
        for (int i = 0; i < 4; i++) {
            int p = lane + 32 * i;
            __nv_bfloat16 hi, lo;
            bsplit(w[i] * inv, hi, lo);
            g_aSh[(size_t)warp * KPAD2 + p] = hi;
            g_aSl[(size_t)warp * KPAD2 + p] = lo;
        }
        if (lane == 0) g_aselfS[warp] = wself * inv;
    } else if (b < 228) {
        __shared__ float sh[8];
        __shared__ float s_inv;
        int p = b - 128;
        float ldp = 0.f, lspp = 0.f;
        #pragma unroll
        for (int ti = 0; ti < 8; ti++) {
            float2 v = *reinterpret_cast<const float2*>(&g_lp[ti][p][0]);
            lspp += v.x;
            ldp += v.y;
        }
        float w[4], sum = 0.f;
        #pragma unroll
        for (int i = 0; i < 4; i++) {
            int s = tid + i * 256;
            float ls = 0.f;
            #pragma unroll
            for (int ti = 0; ti < 8; ti++)
                ls += reinterpret_cast<const float2*>(&g_lp[ti][NP + s][0])->x;
            w[i] = __expf(lrelu(ls + ldp));
            sum += w[i];
        }
        float wself = __expf(lrelu(lspp + ldp));
        #pragma unroll
        for (int o = 16; o > 0; o >>= 1) sum += __shfl_xor_sync(0xffffffffu, sum, o);
        if ((tid & 31) == 0) sh[tid >> 5] = sum;
        __syncthreads();
        if (tid == 0) {
            float ss = 0.f;
            #pragma unroll
            for (int i = 0; i < 8; i++) ss += sh[i];
            s_inv = 1.f / (ss + wself);
        }
        __syncthreads();
        float inv = s_inv;
        #pragma unroll
        for (int i = 0; i < 4; i++) {
            int col = NP + tid + i * 256;
            __nv_bfloat16 hi, lo;
            bsplit(w[i] * inv, hi, lo);
            g_aPh[(size_t)p * MPAD + col] = hi;
            g_aPl[(size_t)p * MPAD + col] = lo;
        }
        if (tid < NP) {
            float dv = (tid == p) ? wself * inv : 0.f;
            __nv_bfloat16 hi, lo;
            bsplit(dv, hi, lo);
            g_aPh[(size_t)p * MPAD + tid] = hi;
            g_aPl[(size_t)p * MPAD + tid] = lo;
        }
        if (tid < MPAD - NN) {
            __nv_bfloat16 z = __float2bfloat16(0.f);
            g_aPh[(size_t)p * MPAD + NN + tid] = z;
            g_aPl[(size_t)p * MPAD + NN + tid] = z;
        }
    } else {
        int p = 100 + (b - 228);
        uint32_t* h = reinterpret_cast<uint32_t*>(g_aPh + (size_t)p * MPAD);
        uint32_t* l = reinterpret_cast<uint32_t*>(g_aPl + (size_t)p * MPAD);
        for (int i = tid; i < MPAD / 2; i += 256) { h[i] = 0u; l[i] = 0u; }
    }
}

// ============================ aggregation GEMM (tensor cores) ============================
// blocks 0..127 sample tiles (K=128) with self-tile prefetch into smem.
// layer 1 only: blocks 128..271 proxy tiles x split-K; 9th arrival finalizes the tile
// (sums partials + bias + relu -> bf16 split into g_Ah/g_Al), replacing k_pfin.
__global__ void __launch_bounds__(256, 2) k_aggm(const float* __restrict__ bias,
                                                 float* __restrict__ hout, int layer) {
    extern __shared__ __align__(16) char sm[];
    int tid = threadIdx.x, wid = tid >> 5, lane = tid & 31;
    int wm = (wid >> 2) * 32, wn = (wid & 3) * 16;
    uint32_t sb = smem_u32(sm);
    int b = blockIdx.x;

    if (b < 128) {
        int m0 = (b >> 3) * 64, n0 = (b & 7) * 64;

        // prefetch fp32 self tile (covered by the mainloop's wait_group 0)
        #pragma unroll
        for (int q = 0; q < 4; q++) {
            int i = tid + q * 256;
            int r = i >> 4, cc = (i & 15) * 4;
            cpa16(sb + 65536 + i * 16, g_HW + (size_t)(NP + m0 + r) * D + n0 + cc);
        }
        asm volatile("cp.async.commit_group;");

        MMA_MAINLOOP(g_aSh, g_aSl, g_Hth, g_Htl, KPAD2, MPAD, 2, 0)

        const float* selfS = reinterpret_cast<const float*>(sm + 65536);
        #pragma unroll
        for (int mt = 0; mt < 2; mt++)
            #pragma unroll
            for (int nt = 0; nt < 2; nt++)
                #pragma unroll
                for (int j = 0; j < 4; j++) {
                    int rl = wm + mt * 16 + (lane >> 2) + (j >> 1) * 8;
                    int cl = wn + nt * 8 + (lane & 3) * 2 + (j & 1);
                    float v = acc[mt][nt][j] + g_aselfS[m0 + rl] * selfS[rl * 64 + cl]
                            + bias[n0 + cl];
                    acc[mt][nt][j] = v > 0.f ? v : 0.f;
                }
        #pragma unroll
        for (int mt = 0; mt < 2; mt++)
            #pragma unroll
            for (int half = 0; half < 2; half++) {
                int r = m0 + wm + mt * 16 + (lane >> 2) + half * 8;
                int arow = (layer == 1) ? (NP + r) : r;
                #pragma unroll
                for (int nt = 0; nt < 2; nt++) {
                    int col = n0 + wn + nt * 8 + (lane & 3) * 2;
                    float v0 = acc[mt][nt][half * 2], v1 = acc[mt][nt][half * 2 + 1];
                    __nv_bfloat16 h0, h1, l0, l1;
                    bsplit(v0, h0, l0); bsplit(v1, h1, l1);
                    *reinterpret_cast<__nv_bfloat162*>(g_Ah + (size_t)arow * D + col) =
                        __nv_bfloat162(h0, h1);
                    *reinterpret_cast<__nv_bfloat162*>(g_Al + (size_t)arow * D + col) =
                        __nv_bfloat162(l0, l1);
                    if (layer == 2)
                        *reinterpret_cast<float2*>(hout + (size_t)r * D + col) =
                            make_float2(v0, v1);
                }
            }
    } else {
        int bb = b - 128;
        int tile = bb & 15;
        int z = bb >> 4;                       // split index 0..8
        int m0 = (tile >> 3) * 64, n0 = (tile & 7) * 64;
        MMA_MAINLOOP(g_aPh, g_aPl, g_Hth, g_Htl, MPAD, MPAD, 2, z * 128)
        float* part = &g_ppart[z][0][0];
        #pragma unroll
        for (int mt = 0; mt < 2; mt++)
            #pragma unroll
            for (int half = 0; half < 2; half++) {
                int p = m0 + wm + mt * 16 + (lane >> 2) + half * 8;
                if (p >= NP) continue;
                #pragma unroll
                for (int nt = 0; nt < 2; nt++) {
                    int col = n0 + wn + nt * 8 + (lane & 3) * 2;
                    *reinterpret_cast<float2*>(part + (size_t)p * D + col) =
                        make_float2(acc[mt][nt][half * 2], acc[mt][nt][half * 2 + 1]);
                }
            }

        // split-K fixup: 9th arrival for this tile finalizes it (replaces k_pfin)
        __shared__ int s_last;
        __threadfence();
        __syncthreads();
        if (tid == 0) {
            unsigned prev = atomicAdd(&g_cntP[tile], 1u);
            s_last = (prev == PSPLIT - 1);
            if (s_last) g_cntP[tile] = 0;   // self-reset for graph replay
        }
        __syncthreads();
        if (s_last) {
            __threadfence();
            // finalize rows m0..m0+63 (p < NP), cols n0..n0+63
            for (int idx = tid; idx < 64 * 32; idx += 256) {
                int r = idx >> 5;
                int p = m0 + r;
                if (p >= NP) continue;
                int c = n0 + (idx & 31) * 2;
                float v0 = 0.f, v1 = 0.f;
                #pragma unroll
                for (int zz = 0; zz < PSPLIT; zz++) {
                    float2 t = __ldcg(reinterpret_cast<const float2*>(&g_ppart[zz][p][c]));
                    v0 += t.x; v1 += t.y;
                }
                v0 += bias[c];     v0 = v0 > 0.f ? v0 : 0.f;
                v1 += bias[c + 1]; v1 = v1 > 0.f ? v1 : 0.f;
                __nv_bfloat16 h0, h1, l0, l1;
                bsplit(v0, h0, l0); bsplit(v1, h1, l1);
                *reinterpret_cast<__nv_bfloat162*>(g_Ah + (size_t)p * D + c) =
                    __nv_bfloat162(h0, h1);
                *reinterpret_cast<__nv_bfloat162*>(g_Al + (size_t)p * D + c) =
                    __nv_bfloat162(l0, l1);
            }
        }
    }
}

// ============================ launch ============================
extern "C" void kernel_launch(void* const* d_in, const int* in_sizes, int n_in,
                              void* d_out, int out_size) {
    const float* x    = (const float*)d_in[0];
    const float* prox = (const float*)d_in[1];
    const float* W1   = (const float*)d_in[2];
    const float* as1  = (const float*)d_in[3];
    const float* ad1  = (const float*)d_in[4];
    const float* b1   = (const float*)d_in[5];
    const float* W2   = (const float*)d_in[6];
    const float* as2  = (const float*)d_in[7];
    const float* ad2  = (const float*)d_in[8];
    const float* b2   = (const float*)d_in[9];
    const float* fcw  = (const float*)d_in[10];
    const float* fcb  = (const float*)d_in[11];
    float* out = (float*)d_out;

    __nv_bfloat16 *pAh, *pAl, *pW1h, *pW1l, *pW2h, *pW2l, *pFCh, *pFCl;
    cudaGetSymbolAddress((void**)&pAh,  g_Ah);
    cudaGetSymbolAddress((void**)&pAl,  g_Al);
    cudaGetSymbolAddress((void**)&pW1h, g_W1h);
    cudaGetSymbolAddress((void**)&pW1l, g_W1l);
    cudaGetSymbolAddress((void**)&pW2h, g_W2h);
    cudaGetSymbolAddress((void**)&pW2l, g_W2l);
    cudaGetSymbolAddress((void**)&pFCh, g_FCh);
    cudaGetSymbolAddress((void**)&pFCl, g_FCl);

    cudaFuncSetAttribute(k_mma,  cudaFuncAttributeMaxDynamicSharedMemorySize, 2 * STAGE_BYTES);
    cudaFuncSetAttribute(k_aggm, cudaFuncAttributeMaxDynamicSharedMemorySize, AGG_SMEM);

    k_setup<<<1152, 256>>>(W1, W2, fcw, x, prox);

    // ---- layer 1
    k_mma<<<dim3(8, 18), 256, 2 * STAGE_BYTES>>>(pAh, pAl, pW1h, pW1l, nullptr, nullptr, 1, as1, ad1);
    k_alpha<<<256, 256>>>(1);
    k_aggm<<<128 + 16 * PSPLIT, 256, AGG_SMEM>>>(b1, nullptr, 1);

    // ---- layer 2 (proxy aggregation unused downstream)
    k_mma<<<dim3(8, 18), 256, 2 * STAGE_BYTES>>>(pAh, pAl, pW2h, pW2l, nullptr, nullptr, 1, as2, ad2);
    k_alpha<<<128, 256>>>(2);
    k_aggm<<<128, 256, AGG_SMEM>>>(b2, out + NS * 100, 2);

    // ---- preds = h @ fc_w + fc_b
    k_mma<<<dim3(2, 16), 256, 2 * STAGE_BYTES>>>(pAh, pAl, pFCh, pFCl, out, fcb, 0, nullptr, nullptr);
}